// round 4
// baseline (speedup 1.0000x reference)
#include <cuda_runtime.h>

#define N_ROWS 131072
#define D      64
#define KFULL  1024
#define KM1    1023
#define TJ     32
#define TPB    128
#define NTILES (KFULL / TJ)

// Scratch (no dynamic allocation allowed)
__device__ float  g_dith[KFULL * D];  // row 1023 = zeros (padding)
__device__ float2 g_cj2[KFULL];       // {||d_j||^2, ||d_j||^2}, entry 1023 = 1e30
__device__ int    g_counts[KFULL];

// ---------- packed f32x2 helpers ----------
__device__ __forceinline__ unsigned long long pk2(float a, float b) {
    unsigned long long r;
    asm("mov.b64 %0, {%1,%2};" : "=l"(r) : "f"(a), "f"(b));
    return r;
}
__device__ __forceinline__ unsigned long long fma2(unsigned long long a,
                                                   unsigned long long b,
                                                   unsigned long long c) {
    unsigned long long d;
    asm("fma.rn.f32x2 %0, %1, %2, %3;" : "=l"(d) : "l"(a), "l"(b), "l"(c));
    return d;
}
__device__ __forceinline__ unsigned long long add2(unsigned long long a,
                                                   unsigned long long b) {
    unsigned long long d;
    asm("add.rn.f32x2 %0, %1, %2;" : "=l"(d) : "l"(a), "l"(b));
    return d;
}
__device__ __forceinline__ unsigned long long mul2(unsigned long long a,
                                                   unsigned long long b) {
    unsigned long long d;
    asm("mul.rn.f32x2 %0, %1, %2;" : "=l"(d) : "l"(a), "l"(b));
    return d;
}
__device__ __forceinline__ float2 upk(unsigned long long r) {
    float2 f;
    asm("mov.b64 {%0,%1}, %2;" : "=f"(f.x), "=f"(f.y) : "l"(r));
    return f;
}

// ---------- prep: dithered codebook (separate RN ops, no FMA contraction) ----------
__global__ void prep_kernel(const float* __restrict__ cb,
                            const float* __restrict__ dither) {
    int idx = blockIdx.x * blockDim.x + threadIdx.x;
    if (idx < KFULL * D) {
        int j = idx / D, k = idx % D;
        float v = 0.0f;
        if (j < KM1) {
            float lo = cb[j * D + k];
            float hi = cb[(j + 1) * D + k];
            float t  = __fsub_rn(hi, lo);
            float u  = __fmul_rn(dither[j], t);
            v        = __fadd_rn(lo, u);
        }
        g_dith[idx] = v;
    }
    if (idx < KFULL) g_counts[idx] = 0;
}

// ---------- ||d_j||^2, sequential fp32 sum, duplicated into float2 ----------
__global__ void cj_kernel() {
    int j = blockIdx.x * blockDim.x + threadIdx.x;
    if (j >= KFULL) return;
    float v;
    if (j >= KM1) {
        v = 1e30f;
    } else {
        float acc = 0.0f;
        #pragma unroll
        for (int k = 0; k < D; k++) {
            float d = g_dith[j * D + k];
            acc = __fadd_rn(acc, __fmul_rn(d, d));
        }
        v = acc;
    }
    g_cj2[j] = make_float2(v, v);
}

// ---------- main: 2 rows/thread, row-packed f32x2 lanes ----------
__global__ void __launch_bounds__(TPB, 3)
main_kernel(const float* __restrict__ z,
            const float* __restrict__ cb,
            const float* __restrict__ dither,
            const float* __restrict__ n1,
            const float* __restrict__ n2,
            float* __restrict__ out) {
    __shared__ __align__(16) float  sdup[TJ * 2 * D];  // duplicated code tile, 16KB
    __shared__ __align__(16) float2 scj[KFULL];        // duplicated cj, 8KB

    const int tid  = threadIdx.x;
    const int rowA = blockIdx.x * (2 * TPB) + tid;
    const int rowB = rowA + TPB;

    // load all cj pairs into shared once (1024 float2 = 512 float4)
    {
        const float4* src = (const float4*)g_cj2;
        float4* dst = (float4*)scj;
        #pragma unroll
        for (int r = 0; r < 4; r++) dst[tid + r * TPB] = src[tid + r * TPB];
    }

    // z rows, packed row-wise: zp[k] = {zA[k], zB[k]}
    unsigned long long zp[D];
    {
        const float4* pa = (const float4*)(z + (size_t)rowA * D);
        const float4* pb = (const float4*)(z + (size_t)rowB * D);
        #pragma unroll
        for (int q = 0; q < 16; q++) {
            float4 va = pa[q];
            float4 vb = pb[q];
            zp[4 * q + 0] = pk2(va.x, vb.x);
            zp[4 * q + 1] = pk2(va.y, vb.y);
            zp[4 * q + 2] = pk2(va.z, vb.z);
            zp[4 * q + 3] = pk2(va.w, vb.w);
        }
    }

    // ||z||^2 per lane, sequential RN (locked order)
    unsigned long long nz2 = 0ull;
    #pragma unroll
    for (int k = 0; k < D; k++) nz2 = fma2(zp[k], zp[k], nz2);

    const unsigned long long negtwo = pk2(-2.0f, -2.0f);

    float bestA = 3.4e38f, bestB = 3.4e38f;
    int   idxA = 0, idxB = 0;

    for (int jt = 0; jt < NTILES; jt++) {
        __syncthreads();
        // duplicate-expand tile into shared: d_k -> {d_k, d_k}
        {
            const float4* src = (const float4*)(g_dith + (size_t)jt * TJ * D);
            float4* dst = (float4*)sdup;
            #pragma unroll
            for (int r = 0; r < (TJ * D / 4) / TPB; r++) {
                int idx = tid + r * TPB;
                float4 v = src[idx];
                float4 a; a.x = v.x; a.y = v.x; a.z = v.y; a.w = v.y;
                float4 b; b.x = v.z; b.y = v.z; b.z = v.w; b.w = v.w;
                dst[2 * idx]     = a;
                dst[2 * idx + 1] = b;
            }
        }
        __syncthreads();

        #pragma unroll 8
        for (int c = 0; c < TJ; c++) {
            const ulonglong2* sp = (const ulonglong2*)(sdup + c * 2 * D);
            // 8 chains: m[e] accumulates k ≡ e (mod 8), lanes = rows A/B
            unsigned long long m0 = 0ull, m1 = 0ull, m2 = 0ull, m3 = 0ull;
            unsigned long long m4 = 0ull, m5 = 0ull, m6 = 0ull, m7 = 0ull;
            #pragma unroll
            for (int q = 0; q < 32; q += 4) {
                ulonglong2 v0 = sp[q + 0];   // k = 2q, 2q+1
                ulonglong2 v1 = sp[q + 1];   // k = 2q+2, 2q+3
                ulonglong2 v2 = sp[q + 2];
                ulonglong2 v3 = sp[q + 3];
                m0 = fma2(zp[2 * q + 0], v0.x, m0);
                m1 = fma2(zp[2 * q + 1], v0.y, m1);
                m2 = fma2(zp[2 * q + 2], v1.x, m2);
                m3 = fma2(zp[2 * q + 3], v1.y, m3);
                m4 = fma2(zp[2 * q + 4], v2.x, m4);
                m5 = fma2(zp[2 * q + 5], v2.y, m5);
                m6 = fma2(zp[2 * q + 6], v3.x, m6);
                m7 = fma2(zp[2 * q + 7], v3.y, m7);
            }
            const int j = jt * TJ + c;
            // locked merge tree, both rows at once
            unsigned long long t01 = add2(m0, m1);
            unsigned long long t23 = add2(m2, m3);
            unsigned long long t45 = add2(m4, m5);
            unsigned long long t67 = add2(m6, m7);
            unsigned long long dot2 = add2(add2(t01, t23), add2(t45, t67));
            // s = RN(RN(nz+cj) + RN(-2*dot))  ==  RN(RN(nz+cj) - RN(2*dot))
            unsigned long long cj2 = *(const unsigned long long*)&scj[j];
            unsigned long long s2 = add2(add2(nz2, cj2), mul2(negtwo, dot2));
            float2 s = upk(s2);
            if (s.x < bestA) { bestA = s.x; idxA = j; }
            if (s.y < bestB) { bestB = s.y; idxB = j; }
        }
    }

    // ---------- epilogue (identical numerics; z reloaded from global) ----------
    #pragma unroll
    for (int rr = 0; rr < 2; rr++) {
        const int row = rr ? rowB : rowA;
        const int i   = rr ? idxB : idxA;
        const float2* zrp = (const float2*)(z + (size_t)row * D);
        const float2* cfp = (const float2*)(cb + (size_t)i * D);
        const float2* csp = (const float2*)(cb + (size_t)(i + 1) * D);
        const float2* ap  = (const float2*)(n1 + (size_t)row * D);
        const float2* bp  = (const float2*)(n2 + (size_t)row * D);
        const float lam = dither[i];

        float sd1 = 0.0f, sr1 = 0.0f, sd2 = 0.0f, sr2 = 0.0f;
        #pragma unroll
        for (int q = 0; q < 32; q++) {
            float2 zz = zrp[q];
            float2 cf = cfp[q], cs = csp[q], av = ap[q], bv = bp[q];
            {
                float d1 = __fsub_rn(cf.x, zz.x);
                float r1 = __fadd_rn(av.x, d1);
                sd1 = __fadd_rn(sd1, __fmul_rn(d1, d1));
                sr1 = __fadd_rn(sr1, __fmul_rn(r1, r1));
                float d2 = __fsub_rn(cs.x, zz.x);
                float r2 = __fadd_rn(bv.x, d2);
                sd2 = __fadd_rn(sd2, __fmul_rn(d2, d2));
                sr2 = __fadd_rn(sr2, __fmul_rn(r2, r2));
            }
            {
                float d1 = __fsub_rn(cf.y, zz.y);
                float r1 = __fadd_rn(av.y, d1);
                sd1 = __fadd_rn(sd1, __fmul_rn(d1, d1));
                sr1 = __fadd_rn(sr1, __fmul_rn(r1, r1));
                float d2 = __fsub_rn(cs.y, zz.y);
                float r2 = __fadd_rn(bv.y, d2);
                sd2 = __fadd_rn(sd2, __fmul_rn(d2, d2));
                sr2 = __fadd_rn(sr2, __fmul_rn(r2, r2));
            }
        }

        float nn1 = fmaxf(__fsqrt_rn(sr1), 1e-12f);
        float nn2 = fmaxf(__fsqrt_rn(sr2), 1e-12f);
        float em1 = __fsqrt_rn(sd1);
        float em2 = __fsqrt_rn(sd2);
        float s1  = __fsub_rn(1.0f, lam);

        float2* op = (float2*)(out + (size_t)row * D);
        #pragma unroll
        for (int q = 0; q < 32; q++) {
            float2 zz = zrp[q];
            float2 cf = cfp[q], cs = csp[q], av = ap[q], bv = bp[q];
            float2 o;
            {
                float d1 = __fsub_rn(cf.x, zz.x);
                float r1 = __fadd_rn(av.x, d1);
                float d2 = __fsub_rn(cs.x, zz.x);
                float r2 = __fadd_rn(bv.x, d2);
                float v1 = __fmul_rn(em1, __fmul_rn(s1,  __fdiv_rn(r1, nn1)));
                float v2 = __fmul_rn(em2, __fmul_rn(lam, __fdiv_rn(r2, nn2)));
                o.x = __fadd_rn(__fadd_rn(zz.x, v1), v2);
            }
            {
                float d1 = __fsub_rn(cf.y, zz.y);
                float r1 = __fadd_rn(av.y, d1);
                float d2 = __fsub_rn(cs.y, zz.y);
                float r2 = __fadd_rn(bv.y, d2);
                float v1 = __fmul_rn(em1, __fmul_rn(s1,  __fdiv_rn(r1, nn1)));
                float v2 = __fmul_rn(em2, __fmul_rn(lam, __fdiv_rn(r2, nn2)));
                o.y = __fadd_rn(__fadd_rn(zz.y, v1), v2);
            }
            op[q] = o;
        }

        out[(size_t)N_ROWS * D + row] = (float)i;
        atomicAdd(&g_counts[i], 1);
    }
}

// ---------- perplexity ----------
__global__ void perp_kernel(float* __restrict__ out) {
    __shared__ float sh[1024];
    int t = threadIdx.x;
    float p = (float)g_counts[t] * (1.0f / 131072.0f);
    sh[t] = (p > 0.0f) ? __fmul_rn(p, logf(p)) : 0.0f;
    __syncthreads();
    for (int s = 512; s > 0; s >>= 1) {
        if (t < s) sh[t] = __fadd_rn(sh[t], sh[t + s]);
        __syncthreads();
    }
    if (t == 0) out[(size_t)N_ROWS * D + N_ROWS] = expf(-sh[0]);
}

extern "C" void kernel_launch(void* const* d_in, const int* in_sizes, int n_in,
                              void* d_out, int out_size) {
    const float* z      = (const float*)d_in[0];
    const float* cb     = (const float*)d_in[1];
    const float* dither = (const float*)d_in[2];
    const float* n1     = (const float*)d_in[3];
    const float* n2     = (const float*)d_in[4];
    float* out = (float*)d_out;

    prep_kernel<<<(KFULL * D + 255) / 256, 256>>>(cb, dither);
    cj_kernel<<<4, 256>>>();
    main_kernel<<<N_ROWS / (2 * TPB), TPB>>>(z, cb, dither, n1, n2, out);
    perp_kernel<<<1, 1024>>>(out);
}

// round 5
// speedup vs baseline: 1.6309x; 1.6309x over previous
#include <cuda_runtime.h>

#define N_ROWS 131072
#define D      64
#define KFULL  1024
#define KM1    1023
#define TJ     32
#define TPB    128
#define NTILES (KFULL / TJ)

// Scratch (no dynamic allocation allowed)
__device__ float  g_dith[KFULL * D];  // row 1023 = zeros (padding)
__device__ float2 g_cj2[KFULL];       // {||d_j||^2, ||d_j||^2}, entry 1023 = 1e30
__device__ int    g_counts[KFULL];

// ---------- packed f32x2 helpers ----------
__device__ __forceinline__ unsigned long long pk2(float a, float b) {
    unsigned long long r;
    asm("mov.b64 %0, {%1,%2};" : "=l"(r) : "f"(a), "f"(b));
    return r;
}
__device__ __forceinline__ unsigned long long fma2(unsigned long long a,
                                                   unsigned long long b,
                                                   unsigned long long c) {
    unsigned long long d;
    asm("fma.rn.f32x2 %0, %1, %2, %3;" : "=l"(d) : "l"(a), "l"(b), "l"(c));
    return d;
}
__device__ __forceinline__ unsigned long long add2(unsigned long long a,
                                                   unsigned long long b) {
    unsigned long long d;
    asm("add.rn.f32x2 %0, %1, %2;" : "=l"(d) : "l"(a), "l"(b));
    return d;
}
__device__ __forceinline__ unsigned long long mul2(unsigned long long a,
                                                   unsigned long long b) {
    unsigned long long d;
    asm("mul.rn.f32x2 %0, %1, %2;" : "=l"(d) : "l"(a), "l"(b));
    return d;
}
__device__ __forceinline__ float2 upk(unsigned long long r) {
    float2 f;
    asm("mov.b64 {%0,%1}, %2;" : "=f"(f.x), "=f"(f.y) : "l"(r));
    return f;
}

// ---------- prep: dithered codebook (separate RN ops, no FMA contraction) ----------
__global__ void prep_kernel(const float* __restrict__ cb,
                            const float* __restrict__ dither) {
    int idx = blockIdx.x * blockDim.x + threadIdx.x;
    if (idx < KFULL * D) {
        int j = idx / D, k = idx % D;
        float v = 0.0f;
        if (j < KM1) {
            float lo = cb[j * D + k];
            float hi = cb[(j + 1) * D + k];
            float t  = __fsub_rn(hi, lo);
            float u  = __fmul_rn(dither[j], t);
            v        = __fadd_rn(lo, u);
        }
        g_dith[idx] = v;
    }
    if (idx < KFULL) g_counts[idx] = 0;
}

// ---------- ||d_j||^2, sequential fp32 sum, duplicated into float2 ----------
__global__ void cj_kernel() {
    int j = blockIdx.x * blockDim.x + threadIdx.x;
    if (j >= KFULL) return;
    float v;
    if (j >= KM1) {
        v = 1e30f;
    } else {
        float acc = 0.0f;
        #pragma unroll
        for (int k = 0; k < D; k++) {
            float d = g_dith[j * D + k];
            acc = __fadd_rn(acc, __fmul_rn(d, d));
        }
        v = acc;
    }
    g_cj2[j] = make_float2(v, v);
}

// ---------- main: 2 rows/thread, row-packed f32x2 lanes, occ 2 (no spills) ----------
__global__ void __launch_bounds__(TPB, 2)
main_kernel(const float* __restrict__ z,
            const float* __restrict__ cb,
            const float* __restrict__ dither,
            const float* __restrict__ n1,
            const float* __restrict__ n2,
            float* __restrict__ out) {
    __shared__ __align__(16) float  sdup[TJ * 2 * D];  // duplicated code tile, 16KB
    __shared__ __align__(16) float2 scj[KFULL];        // duplicated cj, 8KB

    const int tid  = threadIdx.x;
    const int rowA = blockIdx.x * (2 * TPB) + tid;
    const int rowB = rowA + TPB;

    // load all cj pairs into shared once (1024 float2 = 512 float4)
    {
        const float4* src = (const float4*)g_cj2;
        float4* dst = (float4*)scj;
        #pragma unroll
        for (int r = 0; r < 4; r++) dst[tid + r * TPB] = src[tid + r * TPB];
    }

    // z rows, packed row-wise: zp[k] = {zA[k], zB[k]}
    unsigned long long zp[D];
    {
        const float4* pa = (const float4*)(z + (size_t)rowA * D);
        const float4* pb = (const float4*)(z + (size_t)rowB * D);
        #pragma unroll
        for (int q = 0; q < 16; q++) {
            float4 va = pa[q];
            float4 vb = pb[q];
            zp[4 * q + 0] = pk2(va.x, vb.x);
            zp[4 * q + 1] = pk2(va.y, vb.y);
            zp[4 * q + 2] = pk2(va.z, vb.z);
            zp[4 * q + 3] = pk2(va.w, vb.w);
        }
    }

    // ||z||^2 per lane, sequential RN (locked order)
    unsigned long long nz2 = 0ull;
    #pragma unroll
    for (int k = 0; k < D; k++) nz2 = fma2(zp[k], zp[k], nz2);

    const unsigned long long negtwo = pk2(-2.0f, -2.0f);

    float bestA = 3.4e38f, bestB = 3.4e38f;
    int   idxA = 0, idxB = 0;

    for (int jt = 0; jt < NTILES; jt++) {
        __syncthreads();
        // duplicate-expand tile into shared: d_k -> {d_k, d_k}
        {
            const float4* src = (const float4*)(g_dith + (size_t)jt * TJ * D);
            float4* dst = (float4*)sdup;
            #pragma unroll
            for (int r = 0; r < (TJ * D / 4) / TPB; r++) {
                int idx = tid + r * TPB;
                float4 v = src[idx];
                float4 a; a.x = v.x; a.y = v.x; a.z = v.y; a.w = v.y;
                float4 b; b.x = v.z; b.y = v.z; b.z = v.w; b.w = v.w;
                dst[2 * idx]     = a;
                dst[2 * idx + 1] = b;
            }
        }
        __syncthreads();

        #pragma unroll 8
        for (int c = 0; c < TJ; c++) {
            const ulonglong2* sp = (const ulonglong2*)(sdup + c * 2 * D);
            // 8 chains: m[e] accumulates k ≡ e (mod 8), lanes = rows A/B
            unsigned long long m0 = 0ull, m1 = 0ull, m2 = 0ull, m3 = 0ull;
            unsigned long long m4 = 0ull, m5 = 0ull, m6 = 0ull, m7 = 0ull;
            #pragma unroll
            for (int q = 0; q < 32; q += 4) {
                ulonglong2 v0 = sp[q + 0];   // k = 2q, 2q+1
                ulonglong2 v1 = sp[q + 1];   // k = 2q+2, 2q+3
                ulonglong2 v2 = sp[q + 2];
                ulonglong2 v3 = sp[q + 3];
                m0 = fma2(zp[2 * q + 0], v0.x, m0);
                m1 = fma2(zp[2 * q + 1], v0.y, m1);
                m2 = fma2(zp[2 * q + 2], v1.x, m2);
                m3 = fma2(zp[2 * q + 3], v1.y, m3);
                m4 = fma2(zp[2 * q + 4], v2.x, m4);
                m5 = fma2(zp[2 * q + 5], v2.y, m5);
                m6 = fma2(zp[2 * q + 6], v3.x, m6);
                m7 = fma2(zp[2 * q + 7], v3.y, m7);
            }
            const int j = jt * TJ + c;
            // locked merge tree, both rows at once
            unsigned long long t01 = add2(m0, m1);
            unsigned long long t23 = add2(m2, m3);
            unsigned long long t45 = add2(m4, m5);
            unsigned long long t67 = add2(m6, m7);
            unsigned long long dot2 = add2(add2(t01, t23), add2(t45, t67));
            // s = RN(RN(nz+cj) + RN(-2*dot))  ==  RN(RN(nz+cj) - RN(2*dot))
            unsigned long long cj2 = *(const unsigned long long*)&scj[j];
            unsigned long long s2 = add2(add2(nz2, cj2), mul2(negtwo, dot2));
            float2 s = upk(s2);
            if (s.x < bestA) { bestA = s.x; idxA = j; }
            if (s.y < bestB) { bestB = s.y; idxB = j; }
        }
    }

    // ---------- epilogue (identical numerics; z reloaded from global) ----------
    #pragma unroll
    for (int rr = 0; rr < 2; rr++) {
        const int row = rr ? rowB : rowA;
        const int i   = rr ? idxB : idxA;
        const float2* zrp = (const float2*)(z + (size_t)row * D);
        const float2* cfp = (const float2*)(cb + (size_t)i * D);
        const float2* csp = (const float2*)(cb + (size_t)(i + 1) * D);
        const float2* ap  = (const float2*)(n1 + (size_t)row * D);
        const float2* bp  = (const float2*)(n2 + (size_t)row * D);
        const float lam = dither[i];

        float sd1 = 0.0f, sr1 = 0.0f, sd2 = 0.0f, sr2 = 0.0f;
        #pragma unroll
        for (int q = 0; q < 32; q++) {
            float2 zz = zrp[q];
            float2 cf = cfp[q], cs = csp[q], av = ap[q], bv = bp[q];
            {
                float d1 = __fsub_rn(cf.x, zz.x);
                float r1 = __fadd_rn(av.x, d1);
                sd1 = __fadd_rn(sd1, __fmul_rn(d1, d1));
                sr1 = __fadd_rn(sr1, __fmul_rn(r1, r1));
                float d2 = __fsub_rn(cs.x, zz.x);
                float r2 = __fadd_rn(bv.x, d2);
                sd2 = __fadd_rn(sd2, __fmul_rn(d2, d2));
                sr2 = __fadd_rn(sr2, __fmul_rn(r2, r2));
            }
            {
                float d1 = __fsub_rn(cf.y, zz.y);
                float r1 = __fadd_rn(av.y, d1);
                sd1 = __fadd_rn(sd1, __fmul_rn(d1, d1));
                sr1 = __fadd_rn(sr1, __fmul_rn(r1, r1));
                float d2 = __fsub_rn(cs.y, zz.y);
                float r2 = __fadd_rn(bv.y, d2);
                sd2 = __fadd_rn(sd2, __fmul_rn(d2, d2));
                sr2 = __fadd_rn(sr2, __fmul_rn(r2, r2));
            }
        }

        float nn1 = fmaxf(__fsqrt_rn(sr1), 1e-12f);
        float nn2 = fmaxf(__fsqrt_rn(sr2), 1e-12f);
        float em1 = __fsqrt_rn(sd1);
        float em2 = __fsqrt_rn(sd2);
        float s1  = __fsub_rn(1.0f, lam);

        float2* op = (float2*)(out + (size_t)row * D);
        #pragma unroll
        for (int q = 0; q < 32; q++) {
            float2 zz = zrp[q];
            float2 cf = cfp[q], cs = csp[q], av = ap[q], bv = bp[q];
            float2 o;
            {
                float d1 = __fsub_rn(cf.x, zz.x);
                float r1 = __fadd_rn(av.x, d1);
                float d2 = __fsub_rn(cs.x, zz.x);
                float r2 = __fadd_rn(bv.x, d2);
                float v1 = __fmul_rn(em1, __fmul_rn(s1,  __fdiv_rn(r1, nn1)));
                float v2 = __fmul_rn(em2, __fmul_rn(lam, __fdiv_rn(r2, nn2)));
                o.x = __fadd_rn(__fadd_rn(zz.x, v1), v2);
            }
            {
                float d1 = __fsub_rn(cf.y, zz.y);
                float r1 = __fadd_rn(av.y, d1);
                float d2 = __fsub_rn(cs.y, zz.y);
                float r2 = __fadd_rn(bv.y, d2);
                float v1 = __fmul_rn(em1, __fmul_rn(s1,  __fdiv_rn(r1, nn1)));
                float v2 = __fmul_rn(em2, __fmul_rn(lam, __fdiv_rn(r2, nn2)));
                o.y = __fadd_rn(__fadd_rn(zz.y, v1), v2);
            }
            op[q] = o;
        }

        out[(size_t)N_ROWS * D + row] = (float)i;
        atomicAdd(&g_counts[i], 1);
    }
}

// ---------- perplexity ----------
__global__ void perp_kernel(float* __restrict__ out) {
    __shared__ float sh[1024];
    int t = threadIdx.x;
    float p = (float)g_counts[t] * (1.0f / 131072.0f);
    sh[t] = (p > 0.0f) ? __fmul_rn(p, logf(p)) : 0.0f;
    __syncthreads();
    for (int s = 512; s > 0; s >>= 1) {
        if (t < s) sh[t] = __fadd_rn(sh[t], sh[t + s]);
        __syncthreads();
    }
    if (t == 0) out[(size_t)N_ROWS * D + N_ROWS] = expf(-sh[0]);
}

extern "C" void kernel_launch(void* const* d_in, const int* in_sizes, int n_in,
                              void* d_out, int out_size) {
    const float* z      = (const float*)d_in[0];
    const float* cb     = (const float*)d_in[1];
    const float* dither = (const float*)d_in[2];
    const float* n1     = (const float*)d_in[3];
    const float* n2     = (const float*)d_in[4];
    float* out = (float*)d_out;

    prep_kernel<<<(KFULL * D + 255) / 256, 256>>>(cb, dither);
    cj_kernel<<<4, 256>>>();
    main_kernel<<<N_ROWS / (2 * TPB), TPB>>>(z, cb, dither, n1, n2, out);
    perp_kernel<<<1, 1024>>>(out);
}

// round 7
// speedup vs baseline: 2.0692x; 1.2687x over previous
#include <cuda_runtime.h>
#include <cstdint>

#define N_ROWS 131072
#define D      64
#define KFULL  1024
#define KM1    1023
#define TPB    128
#define ROWS_PER_CTA 128
#define CHUNK  64          // codes staged per chunk
#define NCHUNK (KFULL / CHUNK)
#define BSTRIDE 68         // padded float stride for code rows in shared

// device scratch (no dynamic allocation allowed)
__device__ float g_dith[KFULL * D];   // exact dithered codebook (row 1023 = 0)
__device__ float g_dh[KFULL * D];     // tf32 hi split
__device__ float g_dl[KFULL * D];     // tf32 lo split
__device__ float g_cj[KFULL];         // ||d_j||^2 locked-sequential; [1023]=1e30
__device__ int   g_counts[KFULL];

// ---------------- helpers ----------------
__device__ __forceinline__ uint32_t f2tf32(float v) {
    uint32_t r;
    asm("cvt.rna.tf32.f32 %0, %1;" : "=r"(r) : "f"(v));
    return r;
}
__device__ __forceinline__ void tf32_split(float v, uint32_t& h, uint32_t& l) {
    h = f2tf32(v);
    l = f2tf32(__fsub_rn(v, __uint_as_float(h)));
}
__device__ __forceinline__ void mma8(float* d, const uint32_t* a,
                                     uint32_t b0, uint32_t b1) {
    asm volatile(
        "mma.sync.aligned.m16n8k8.row.col.f32.tf32.tf32.f32 "
        "{%0,%1,%2,%3}, {%4,%5,%6,%7}, {%8,%9}, {%0,%1,%2,%3};"
        : "+f"(d[0]), "+f"(d[1]), "+f"(d[2]), "+f"(d[3])
        : "r"(a[0]), "r"(a[1]), "r"(a[2]), "r"(a[3]), "r"(b0), "r"(b1));
}
// sorted top-3 insert, strict < (preserves first-index among equals)
__device__ __forceinline__ void ins3(float (&ms)[3], int (&mj)[3], float s, int j) {
    if (s < ms[2]) {
        if (s < ms[1]) {
            ms[2] = ms[1]; mj[2] = mj[1];
            if (s < ms[0]) { ms[1] = ms[0]; mj[1] = mj[0]; ms[0] = s; mj[0] = j; }
            else           { ms[1] = s; mj[1] = j; }
        } else { ms[2] = s; mj[2] = j; }
    }
}

// ---------- prep: dithered codebook (locked RN ops), tf32 split, cj ----------
__global__ void prep_kernel(const float* __restrict__ cb,
                            const float* __restrict__ dither) {
    int j = blockIdx.x * blockDim.x + threadIdx.x;
    if (j >= KFULL) return;
    g_counts[j] = 0;
    if (j < KM1) {
        float dj = dither[j];
        float acc = 0.0f;
        #pragma unroll 8
        for (int k = 0; k < D; k++) {
            float lo = cb[j * D + k];
            float hi = cb[(j + 1) * D + k];
            float dv = __fadd_rn(lo, __fmul_rn(dj, __fsub_rn(hi, lo)));
            g_dith[j * D + k] = dv;
            uint32_t h, l;
            tf32_split(dv, h, l);
            g_dh[j * D + k] = __uint_as_float(h);
            g_dl[j * D + k] = __uint_as_float(l);
            acc = __fadd_rn(acc, __fmul_rn(dv, dv));
        }
        g_cj[j] = acc;
    } else {
        #pragma unroll 8
        for (int k = 0; k < D; k++) {
            g_dith[j * D + k] = 0.0f;
            g_dh[j * D + k]   = 0.0f;
            g_dl[j * D + k]   = 0.0f;
        }
        g_cj[j] = 1e30f;
    }
}

// ---------- main: tf32 mma.sync prefilter + exact rescore + epilogue ----------
__global__ void __launch_bounds__(TPB)
main_kernel(const float* __restrict__ z,
            const float* __restrict__ cb,
            const float* __restrict__ dither,
            const float* __restrict__ n1,
            const float* __restrict__ n2,
            float* __restrict__ out) {
    __shared__ __align__(16) float sh_bh[CHUNK * BSTRIDE];  // 17408 B
    __shared__ __align__(16) float sh_bl[CHUNK * BSTRIDE];  // 17408 B
    __shared__ float sh_cj[CHUNK];                          // 256 B
    __shared__ float sh_cs[ROWS_PER_CTA * 12];              // 6144 B
    __shared__ int   sh_ci[ROWS_PER_CTA * 12];              // 6144 B

    const int tid = threadIdx.x;
    const int w   = tid >> 5;          // warp 0..3
    const int lane = tid & 31;
    const int g   = lane >> 2;         // groupID 0..7
    const int tig = lane & 3;          // thread-in-group 0..3

    // ---- A fragments: z rows for this warp (32 rows), tf32 hi/lo ----
    const float* zb = z + (size_t)(blockIdx.x * ROWS_PER_CTA + w * 32) * D;
    uint32_t ah[2][8][4], al[2][8][4];
    #pragma unroll
    for (int m = 0; m < 2; m++) {
        #pragma unroll
        for (int s = 0; s < 8; s++) {
            int r0 = m * 16 + g, r1 = r0 + 8;
            int k0 = s * 8 + tig, k1 = k0 + 4;
            tf32_split(zb[r0 * D + k0], ah[m][s][0], al[m][s][0]);
            tf32_split(zb[r1 * D + k0], ah[m][s][1], al[m][s][1]);
            tf32_split(zb[r0 * D + k1], ah[m][s][2], al[m][s][2]);
            tf32_split(zb[r1 * D + k1], ah[m][s][3], al[m][s][3]);
        }
    }

    // per-thread top-3 candidates for 4 rows
    float ms[4][3];
    int   mj[4][3];
    #pragma unroll
    for (int r = 0; r < 4; r++) {
        #pragma unroll
        for (int k = 0; k < 3; k++) { ms[r][k] = 3.4e38f; mj[r][k] = 0; }
    }

    for (int ch = 0; ch < NCHUNK; ch++) {
        __syncthreads();
        // stage chunk (64 codes) hi/lo into padded shared + cj
        {
            const float4* srcH = (const float4*)(g_dh + (size_t)ch * CHUNK * D);
            const float4* srcL = (const float4*)(g_dl + (size_t)ch * CHUNK * D);
            #pragma unroll
            for (int i = 0; i < 8; i++) {
                int q = tid + i * TPB;           // float4 index 0..1023
                int code = q >> 4, kq = q & 15;
                *(float4*)(sh_bh + code * BSTRIDE + kq * 4) = srcH[q];
                *(float4*)(sh_bl + code * BSTRIDE + kq * 4) = srcL[q];
            }
            if (tid < CHUNK) sh_cj[tid] = g_cj[ch * CHUNK + tid];
        }
        __syncthreads();

        for (int t = 0; t < 8; t++) {            // 8 code-tiles of 8
            float acc0[4] = {0.f, 0.f, 0.f, 0.f};
            float acc1[4] = {0.f, 0.f, 0.f, 0.f};
            #pragma unroll
            for (int s = 0; s < 8; s++) {
                int bbase = (t * 8 + g) * BSTRIDE + s * 8 + tig;
                uint32_t bh0 = __float_as_uint(sh_bh[bbase]);
                uint32_t bh1 = __float_as_uint(sh_bh[bbase + 4]);
                uint32_t bl0 = __float_as_uint(sh_bl[bbase]);
                uint32_t bl1 = __float_as_uint(sh_bl[bbase + 4]);
                mma8(acc0, ah[0][s], bh0, bh1);
                mma8(acc1, ah[1][s], bh0, bh1);
                mma8(acc0, al[0][s], bh0, bh1);
                mma8(acc1, al[1][s], bh0, bh1);
                mma8(acc0, ah[0][s], bl0, bl1);
                mma8(acc1, ah[1][s], bl0, bl1);
            }
            int j0 = ch * CHUNK + t * 8 + tig * 2;
            int j1 = j0 + 1;
            float cj0 = sh_cj[t * 8 + tig * 2];
            float cj1 = sh_cj[t * 8 + tig * 2 + 1];
            // fine scores f = cj - 2*dot (approx; exact rescore later)
            ins3(ms[0], mj[0], __fmaf_rn(-2.f, acc0[0], cj0), j0);
            ins3(ms[0], mj[0], __fmaf_rn(-2.f, acc0[1], cj1), j1);
            ins3(ms[1], mj[1], __fmaf_rn(-2.f, acc0[2], cj0), j0);
            ins3(ms[1], mj[1], __fmaf_rn(-2.f, acc0[3], cj1), j1);
            ins3(ms[2], mj[2], __fmaf_rn(-2.f, acc1[0], cj0), j0);
            ins3(ms[2], mj[2], __fmaf_rn(-2.f, acc1[1], cj1), j1);
            ins3(ms[3], mj[3], __fmaf_rn(-2.f, acc1[2], cj0), j0);
            ins3(ms[3], mj[3], __fmaf_rn(-2.f, acc1[3], cj1), j1);
        }
    }

    // write candidates: row owned by (w, mtile, g, sub); 4 lanes x 3 slots = 12
    #pragma unroll
    for (int r = 0; r < 4; r++) {
        int lrow = w * 32 + (r >> 1) * 16 + (r & 1) * 8 + g;
        int base = lrow * 12 + tig * 3;
        #pragma unroll
        for (int k = 0; k < 3; k++) { sh_cs[base + k] = ms[r][k]; sh_ci[base + k] = mj[r][k]; }
    }
    __syncthreads();

    // ---------- exact rescore (locked numerics) ----------
    const int row = blockIdx.x * ROWS_PER_CTA + tid;
    float zr[D];
    {
        const float4* zp = (const float4*)(z + (size_t)row * D);
        #pragma unroll
        for (int q = 0; q < 16; q++) {
            float4 v = zp[q];
            zr[4 * q + 0] = v.x; zr[4 * q + 1] = v.y;
            zr[4 * q + 2] = v.z; zr[4 * q + 3] = v.w;
        }
    }
    float nz = 0.0f;
    #pragma unroll
    for (int k = 0; k < D; k++) nz = __fadd_rn(nz, __fmul_rn(zr[k], zr[k]));

    float minf = 3.4e38f;
    #pragma unroll
    for (int k = 0; k < 12; k++) minf = fminf(minf, sh_cs[tid * 12 + k]);
    const float thr = minf + 6e-5f;

    float best = 3.4e38f;
    int   bj   = 0x7FFFFFFF;
    for (int k = 0; k < 12; k++) {
        float fs = sh_cs[tid * 12 + k];
        if (fs <= thr) {
            int j = sh_ci[tid * 12 + k];
            const float* dj = g_dith + (size_t)j * D;
            float c0 = 0.f, c1 = 0.f, c2 = 0.f, c3 = 0.f;
            float c4 = 0.f, c5 = 0.f, c6 = 0.f, c7 = 0.f;
            #pragma unroll
            for (int kk = 0; kk < D; kk += 8) {
                c0 = __fmaf_rn(zr[kk + 0], dj[kk + 0], c0);
                c1 = __fmaf_rn(zr[kk + 1], dj[kk + 1], c1);
                c2 = __fmaf_rn(zr[kk + 2], dj[kk + 2], c2);
                c3 = __fmaf_rn(zr[kk + 3], dj[kk + 3], c3);
                c4 = __fmaf_rn(zr[kk + 4], dj[kk + 4], c4);
                c5 = __fmaf_rn(zr[kk + 5], dj[kk + 5], c5);
                c6 = __fmaf_rn(zr[kk + 6], dj[kk + 6], c6);
                c7 = __fmaf_rn(zr[kk + 7], dj[kk + 7], c7);
            }
            float dot = __fadd_rn(
                __fadd_rn(__fadd_rn(c0, c1), __fadd_rn(c2, c3)),
                __fadd_rn(__fadd_rn(c4, c5), __fadd_rn(c6, c7)));
            float s = __fsub_rn(__fadd_rn(nz, g_cj[j]), __fmul_rn(2.0f, dot));
            if (s < best || (s == best && j < bj)) { best = s; bj = j; }
        }
    }

    // ---------- epilogue (proven R2 numerics) ----------
    {
        const int i = bj;
        const float2* cfp = (const float2*)(cb + (size_t)i * D);
        const float2* csp = (const float2*)(cb + (size_t)(i + 1) * D);
        const float2* ap  = (const float2*)(n1 + (size_t)row * D);
        const float2* bp  = (const float2*)(n2 + (size_t)row * D);
        const float lam = dither[i];

        float sd1 = 0.0f, sr1 = 0.0f, sd2 = 0.0f, sr2 = 0.0f;
        #pragma unroll
        for (int q = 0; q < 32; q++) {
            float zx = zr[2 * q], zy = zr[2 * q + 1];
            float2 cf = cfp[q], cs = csp[q], av = ap[q], bv = bp[q];
            {
                float d1 = __fsub_rn(cf.x, zx);
                float r1 = __fadd_rn(av.x, d1);
                sd1 = __fadd_rn(sd1, __fmul_rn(d1, d1));
                sr1 = __fadd_rn(sr1, __fmul_rn(r1, r1));
                float d2 = __fsub_rn(cs.x, zx);
                float r2 = __fadd_rn(bv.x, d2);
                sd2 = __fadd_rn(sd2, __fmul_rn(d2, d2));
                sr2 = __fadd_rn(sr2, __fmul_rn(r2, r2));
            }
            {
                float d1 = __fsub_rn(cf.y, zy);
                float r1 = __fadd_rn(av.y, d1);
                sd1 = __fadd_rn(sd1, __fmul_rn(d1, d1));
                sr1 = __fadd_rn(sr1, __fmul_rn(r1, r1));
                float d2 = __fsub_rn(cs.y, zy);
                float r2 = __fadd_rn(bv.y, d2);
                sd2 = __fadd_rn(sd2, __fmul_rn(d2, d2));
                sr2 = __fadd_rn(sr2, __fmul_rn(r2, r2));
            }
        }

        float nn1 = fmaxf(__fsqrt_rn(sr1), 1e-12f);
        float nn2 = fmaxf(__fsqrt_rn(sr2), 1e-12f);
        float em1 = __fsqrt_rn(sd1);
        float em2 = __fsqrt_rn(sd2);
        float s1  = __fsub_rn(1.0f, lam);

        float2* op = (float2*)(out + (size_t)row * D);
        #pragma unroll
        for (int q = 0; q < 32; q++) {
            float zx = zr[2 * q], zy = zr[2 * q + 1];
            float2 cf = cfp[q], cs = csp[q], av = ap[q], bv = bp[q];
            float2 o;
            {
                float d1 = __fsub_rn(cf.x, zx);
                float r1 = __fadd_rn(av.x, d1);
                float d2 = __fsub_rn(cs.x, zx);
                float r2 = __fadd_rn(bv.x, d2);
                float v1 = __fmul_rn(em1, __fmul_rn(s1,  __fdiv_rn(r1, nn1)));
                float v2 = __fmul_rn(em2, __fmul_rn(lam, __fdiv_rn(r2, nn2)));
                o.x = __fadd_rn(__fadd_rn(zx, v1), v2);
            }
            {
                float d1 = __fsub_rn(cf.y, zy);
                float r1 = __fadd_rn(av.y, d1);
                float d2 = __fsub_rn(cs.y, zy);
                float r2 = __fadd_rn(bv.y, d2);
                float v1 = __fmul_rn(em1, __fmul_rn(s1,  __fdiv_rn(r1, nn1)));
                float v2 = __fmul_rn(em2, __fmul_rn(lam, __fdiv_rn(r2, nn2)));
                o.y = __fadd_rn(__fadd_rn(zy, v1), v2);
            }
            op[q] = o;
        }

        out[(size_t)N_ROWS * D + row] = (float)i;
        atomicAdd(&g_counts[i], 1);
    }
}

// ---------- perplexity ----------
__global__ void perp_kernel(float* __restrict__ out) {
    __shared__ float sh[1024];
    int t = threadIdx.x;
    float p = (float)g_counts[t] * (1.0f / 131072.0f);
    sh[t] = (p > 0.0f) ? __fmul_rn(p, logf(p)) : 0.0f;
    __syncthreads();
    for (int s = 512; s > 0; s >>= 1) {
        if (t < s) sh[t] = __fadd_rn(sh[t], sh[t + s]);
        __syncthreads();
    }
    if (t == 0) out[(size_t)N_ROWS * D + N_ROWS] = expf(-sh[0]);
}

extern "C" void kernel_launch(void* const* d_in, const int* in_sizes, int n_in,
                              void* d_out, int out_size) {
    const float* z      = (const float*)d_in[0];
    const float* cb     = (const float*)d_in[1];
    const float* dither = (const float*)d_in[2];
    const float* n1     = (const float*)d_in[3];
    const float* n2     = (const float*)d_in[4];
    float* out = (float*)d_out;

    prep_kernel<<<KFULL / 128, 128>>>(cb, dither);
    main_kernel<<<N_ROWS / ROWS_PER_CTA, TPB>>>(z, cb, dither, n1, n2, out);
    perp_kernel<<<1, 1024>>>(out);
}

// round 8
// speedup vs baseline: 2.6681x; 1.2894x over previous
#include <cuda_runtime.h>
#include <cuda_bf16.h>
#include <cstdint>

#define N_ROWS 131072
#define D      64
#define KFULL  1024
#define KM1    1023
#define TPB    128
#define ROWS_PER_CTA 128
#define CHUNK  64
#define NCHUNK (KFULL / CHUNK)
#define BSTR   72            // padded bf16 stride per code row (conflict-free)

// device scratch (no dynamic allocation allowed)
__device__ float          g_dith[KFULL * D];   // exact dithered codebook
__device__ __nv_bfloat16  g_dhb[KFULL * D];    // bf16 hi split
__device__ __nv_bfloat16  g_dlb[KFULL * D];    // bf16 lo split
__device__ float          g_cj[KFULL];         // ||d_j||^2 locked; [>=1023]=1e30
__device__ int            g_counts[KFULL];

// ---------------- helpers ----------------
__device__ __forceinline__ uint32_t bfpack(float lo, float hi) {
    uint32_t r;
    asm("cvt.rn.bf16x2.f32 %0, %1, %2;" : "=r"(r) : "f"(hi), "f"(lo));
    return r;
}
// split float2 -> packed bf16 hi pair + lo pair
__device__ __forceinline__ void bsplit2(float2 v, uint32_t& h, uint32_t& l) {
    float h0 = __bfloat162float(__float2bfloat16_rn(v.x));
    float h1 = __bfloat162float(__float2bfloat16_rn(v.y));
    h = bfpack(h0, h1);
    l = bfpack(__fsub_rn(v.x, h0), __fsub_rn(v.y, h1));
}
__device__ __forceinline__ void mma16(float* d, const uint32_t* a,
                                      uint32_t b0, uint32_t b1) {
    asm volatile(
        "mma.sync.aligned.m16n8k16.row.col.f32.bf16.bf16.f32 "
        "{%0,%1,%2,%3}, {%4,%5,%6,%7}, {%8,%9}, {%0,%1,%2,%3};"
        : "+f"(d[0]), "+f"(d[1]), "+f"(d[2]), "+f"(d[3])
        : "r"(a[0]), "r"(a[1]), "r"(a[2]), "r"(a[3]), "r"(b0), "r"(b1));
}
__device__ __forceinline__ void ins3(float (&ms)[3], int (&mj)[3], float s, int j) {
    if (s < ms[2]) {
        if (s < ms[1]) {
            ms[2] = ms[1]; mj[2] = mj[1];
            if (s < ms[0]) { ms[1] = ms[0]; mj[1] = mj[0]; ms[0] = s; mj[0] = j; }
            else           { ms[1] = s; mj[1] = j; }
        } else { ms[2] = s; mj[2] = j; }
    }
}

// ---------- prep 1: elementwise dithered codebook + bf16 splits ----------
__global__ void split_kernel(const float* __restrict__ cb,
                             const float* __restrict__ dither) {
    int idx = blockIdx.x * blockDim.x + threadIdx.x;
    if (idx >= KFULL * D) return;
    int j = idx >> 6;
    float dv = 0.0f;
    if (j < KM1) {
        int k = idx & 63;
        float lo = cb[j * D + k];
        float hi = cb[(j + 1) * D + k];
        dv = __fadd_rn(lo, __fmul_rn(dither[j], __fsub_rn(hi, lo)));
    }
    g_dith[idx] = dv;
    __nv_bfloat16 h = __float2bfloat16_rn(dv);
    float hf = __bfloat162float(h);
    g_dhb[idx] = h;
    g_dlb[idx] = __float2bfloat16_rn(__fsub_rn(dv, hf));
    if (idx < KFULL) g_counts[idx] = 0;
}

// ---------- prep 2: ||d_j||^2 locked sequential ----------
__global__ void cj_kernel() {
    int j = blockIdx.x * blockDim.x + threadIdx.x;
    if (j >= KFULL) return;
    if (j >= KM1) { g_cj[j] = 1e30f; return; }
    float acc = 0.0f;
    #pragma unroll 8
    for (int k = 0; k < D; k++) {
        float d = g_dith[j * D + k];
        acc = __fadd_rn(acc, __fmul_rn(d, d));
    }
    g_cj[j] = acc;
}

// ---------- main: bf16 3-pass mma prefilter + exact rescore + epilogue ----------
__global__ void __launch_bounds__(TPB)
main_kernel(const float* __restrict__ z,
            const float* __restrict__ cb,
            const float* __restrict__ dither,
            const float* __restrict__ n1,
            const float* __restrict__ n2,
            float* __restrict__ out) {
    __shared__ __align__(16) __nv_bfloat16 sh_bh[CHUNK * BSTR];  // 9216 B
    __shared__ __align__(16) __nv_bfloat16 sh_bl[CHUNK * BSTR];  // 9216 B
    __shared__ float sh_cj[CHUNK];
    __shared__ float sh_cs[ROWS_PER_CTA * 12];
    __shared__ int   sh_ci[ROWS_PER_CTA * 12];

    const int tid  = threadIdx.x;
    const int w    = tid >> 5;
    const int lane = tid & 31;
    const int g    = lane >> 2;
    const int tig  = lane & 3;

    // ---- A fragments: 32 z-rows per warp, bf16 hi/lo, m16n8k16 layout ----
    const float* zb = z + (size_t)(blockIdx.x * ROWS_PER_CTA + w * 32) * D;
    uint32_t ah[2][4][4], al[2][4][4];
    #pragma unroll
    for (int m = 0; m < 2; m++) {
        #pragma unroll
        for (int s = 0; s < 4; s++) {
            int r0 = m * 16 + g, r1 = r0 + 8;
            int kb = s * 16 + tig * 2;
            bsplit2(*(const float2*)(zb + r0 * D + kb),     ah[m][s][0], al[m][s][0]);
            bsplit2(*(const float2*)(zb + r1 * D + kb),     ah[m][s][1], al[m][s][1]);
            bsplit2(*(const float2*)(zb + r0 * D + kb + 8), ah[m][s][2], al[m][s][2]);
            bsplit2(*(const float2*)(zb + r1 * D + kb + 8), ah[m][s][3], al[m][s][3]);
        }
    }

    float ms[4][3];
    int   mj[4][3];
    #pragma unroll
    for (int r = 0; r < 4; r++)
        #pragma unroll
        for (int k = 0; k < 3; k++) { ms[r][k] = 3.4e38f; mj[r][k] = 0; }

    for (int ch = 0; ch < NCHUNK; ch++) {
        __syncthreads();
        // stage 64 codes (hi/lo bf16) into padded shared + cj
        {
            const uint2* srcH = (const uint2*)(g_dhb + (size_t)ch * CHUNK * D);
            const uint2* srcL = (const uint2*)(g_dlb + (size_t)ch * CHUNK * D);
            #pragma unroll
            for (int i = 0; i < 8; i++) {
                int q = tid + i * TPB;        // uint2 index: 64 codes x 16
                int code = q >> 4, kq = q & 15;
                *(uint2*)(sh_bh + code * BSTR + kq * 4) = srcH[q];
                *(uint2*)(sh_bl + code * BSTR + kq * 4) = srcL[q];
            }
            if (tid < CHUNK) sh_cj[tid] = g_cj[ch * CHUNK + tid];
        }
        __syncthreads();

        for (int t = 0; t < 8; t++) {
            float acc0[4] = {0.f, 0.f, 0.f, 0.f};
            float acc1[4] = {0.f, 0.f, 0.f, 0.f};
            #pragma unroll
            for (int s = 0; s < 4; s++) {
                const __nv_bfloat16* bp = sh_bh + (t * 8 + g) * BSTR + s * 16 + tig * 2;
                const __nv_bfloat16* lp = sh_bl + (t * 8 + g) * BSTR + s * 16 + tig * 2;
                uint32_t bh0 = *(const uint32_t*)bp;
                uint32_t bh1 = *(const uint32_t*)(bp + 8);
                uint32_t bl0 = *(const uint32_t*)lp;
                uint32_t bl1 = *(const uint32_t*)(lp + 8);
                mma16(acc0, ah[0][s], bh0, bh1);
                mma16(acc1, ah[1][s], bh0, bh1);
                mma16(acc0, al[0][s], bh0, bh1);
                mma16(acc1, al[1][s], bh0, bh1);
                mma16(acc0, ah[0][s], bl0, bl1);
                mma16(acc1, ah[1][s], bl0, bl1);
            }
            int j0 = ch * CHUNK + t * 8 + tig * 2;
            int j1 = j0 + 1;
            float cj0 = sh_cj[t * 8 + tig * 2];
            float cj1 = sh_cj[t * 8 + tig * 2 + 1];
            ins3(ms[0], mj[0], __fmaf_rn(-2.f, acc0[0], cj0), j0);
            ins3(ms[0], mj[0], __fmaf_rn(-2.f, acc0[1], cj1), j1);
            ins3(ms[1], mj[1], __fmaf_rn(-2.f, acc0[2], cj0), j0);
            ins3(ms[1], mj[1], __fmaf_rn(-2.f, acc0[3], cj1), j1);
            ins3(ms[2], mj[2], __fmaf_rn(-2.f, acc1[0], cj0), j0);
            ins3(ms[2], mj[2], __fmaf_rn(-2.f, acc1[1], cj1), j1);
            ins3(ms[3], mj[3], __fmaf_rn(-2.f, acc1[2], cj0), j0);
            ins3(ms[3], mj[3], __fmaf_rn(-2.f, acc1[3], cj1), j1);
        }
    }

    #pragma unroll
    for (int r = 0; r < 4; r++) {
        int lrow = w * 32 + (r >> 1) * 16 + (r & 1) * 8 + g;
        int base = lrow * 12 + tig * 3;
        #pragma unroll
        for (int k = 0; k < 3; k++) { sh_cs[base + k] = ms[r][k]; sh_ci[base + k] = mj[r][k]; }
    }
    __syncthreads();

    // ---------- exact rescore (locked numerics) ----------
    const int row = blockIdx.x * ROWS_PER_CTA + tid;
    float zr[D];
    {
        const float4* zp = (const float4*)(z + (size_t)row * D);
        #pragma unroll
        for (int q = 0; q < 16; q++) {
            float4 v = zp[q];
            zr[4 * q + 0] = v.x; zr[4 * q + 1] = v.y;
            zr[4 * q + 2] = v.z; zr[4 * q + 3] = v.w;
        }
    }
    float nz = 0.0f;
    #pragma unroll
    for (int k = 0; k < D; k++) nz = __fadd_rn(nz, __fmul_rn(zr[k], zr[k]));

    float minf = 3.4e38f;
    #pragma unroll
    for (int k = 0; k < 12; k++) minf = fminf(minf, sh_cs[tid * 12 + k]);
    const float thr = minf + 6e-5f;

    float best = 3.4e38f;
    int   bj   = 0x7FFFFFFF;
    for (int k = 0; k < 12; k++) {
        float fs = sh_cs[tid * 12 + k];
        if (fs <= thr) {
            int j = sh_ci[tid * 12 + k];
            const float* dj = g_dith + (size_t)j * D;
            float c0 = 0.f, c1 = 0.f, c2 = 0.f, c3 = 0.f;
            float c4 = 0.f, c5 = 0.f, c6 = 0.f, c7 = 0.f;
            #pragma unroll
            for (int kk = 0; kk < D; kk += 8) {
                c0 = __fmaf_rn(zr[kk + 0], dj[kk + 0], c0);
                c1 = __fmaf_rn(zr[kk + 1], dj[kk + 1], c1);
                c2 = __fmaf_rn(zr[kk + 2], dj[kk + 2], c2);
                c3 = __fmaf_rn(zr[kk + 3], dj[kk + 3], c3);
                c4 = __fmaf_rn(zr[kk + 4], dj[kk + 4], c4);
                c5 = __fmaf_rn(zr[kk + 5], dj[kk + 5], c5);
                c6 = __fmaf_rn(zr[kk + 6], dj[kk + 6], c6);
                c7 = __fmaf_rn(zr[kk + 7], dj[kk + 7], c7);
            }
            float dot = __fadd_rn(
                __fadd_rn(__fadd_rn(c0, c1), __fadd_rn(c2, c3)),
                __fadd_rn(__fadd_rn(c4, c5), __fadd_rn(c6, c7)));
            float s = __fsub_rn(__fadd_rn(nz, g_cj[j]), __fmul_rn(2.0f, dot));
            if (s < best || (s == best && j < bj)) { best = s; bj = j; }
        }
    }

    // ---------- epilogue (proven R2 numerics) ----------
    {
        const int i = bj;
        const float2* cfp = (const float2*)(cb + (size_t)i * D);
        const float2* csp = (const float2*)(cb + (size_t)(i + 1) * D);
        const float2* ap  = (const float2*)(n1 + (size_t)row * D);
        const float2* bp  = (const float2*)(n2 + (size_t)row * D);
        const float lam = dither[i];

        float sd1 = 0.0f, sr1 = 0.0f, sd2 = 0.0f, sr2 = 0.0f;
        #pragma unroll
        for (int q = 0; q < 32; q++) {
            float zx = zr[2 * q], zy = zr[2 * q + 1];
            float2 cf = cfp[q], cs = csp[q], av = ap[q], bv = bp[q];
            {
                float d1 = __fsub_rn(cf.x, zx);
                float r1 = __fadd_rn(av.x, d1);
                sd1 = __fadd_rn(sd1, __fmul_rn(d1, d1));
                sr1 = __fadd_rn(sr1, __fmul_rn(r1, r1));
                float d2 = __fsub_rn(cs.x, zx);
                float r2 = __fadd_rn(bv.x, d2);
                sd2 = __fadd_rn(sd2, __fmul_rn(d2, d2));
                sr2 = __fadd_rn(sr2, __fmul_rn(r2, r2));
            }
            {
                float d1 = __fsub_rn(cf.y, zy);
                float r1 = __fadd_rn(av.y, d1);
                sd1 = __fadd_rn(sd1, __fmul_rn(d1, d1));
                sr1 = __fadd_rn(sr1, __fmul_rn(r1, r1));
                float d2 = __fsub_rn(cs.y, zy);
                float r2 = __fadd_rn(bv.y, d2);
                sd2 = __fadd_rn(sd2, __fmul_rn(d2, d2));
                sr2 = __fadd_rn(sr2, __fmul_rn(r2, r2));
            }
        }

        float nn1 = fmaxf(__fsqrt_rn(sr1), 1e-12f);
        float nn2 = fmaxf(__fsqrt_rn(sr2), 1e-12f);
        float em1 = __fsqrt_rn(sd1);
        float em2 = __fsqrt_rn(sd2);
        float s1  = __fsub_rn(1.0f, lam);

        float2* op = (float2*)(out + (size_t)row * D);
        #pragma unroll
        for (int q = 0; q < 32; q++) {
            float zx = zr[2 * q], zy = zr[2 * q + 1];
            float2 cf = cfp[q], cs = csp[q], av = ap[q], bv = bp[q];
            float2 o;
            {
                float d1 = __fsub_rn(cf.x, zx);
                float r1 = __fadd_rn(av.x, d1);
                float d2 = __fsub_rn(cs.x, zx);
                float r2 = __fadd_rn(bv.x, d2);
                float v1 = __fmul_rn(em1, __fmul_rn(s1,  __fdiv_rn(r1, nn1)));
                float v2 = __fmul_rn(em2, __fmul_rn(lam, __fdiv_rn(r2, nn2)));
                o.x = __fadd_rn(__fadd_rn(zx, v1), v2);
            }
            {
                float d1 = __fsub_rn(cf.y, zy);
                float r1 = __fadd_rn(av.y, d1);
                float d2 = __fsub_rn(cs.y, zy);
                float r2 = __fadd_rn(bv.y, d2);
                float v1 = __fmul_rn(em1, __fmul_rn(s1,  __fdiv_rn(r1, nn1)));
                float v2 = __fmul_rn(em2, __fmul_rn(lam, __fdiv_rn(r2, nn2)));
                o.y = __fadd_rn(__fadd_rn(zy, v1), v2);
            }
            op[q] = o;
        }

        out[(size_t)N_ROWS * D + row] = (float)i;
        atomicAdd(&g_counts[i], 1);
    }
}

// ---------- perplexity ----------
__global__ void perp_kernel(float* __restrict__ out) {
    __shared__ float sh[1024];
    int t = threadIdx.x;
    float p = (float)g_counts[t] * (1.0f / 131072.0f);
    sh[t] = (p > 0.0f) ? __fmul_rn(p, logf(p)) : 0.0f;
    __syncthreads();
    for (int s = 512; s > 0; s >>= 1) {
        if (t < s) sh[t] = __fadd_rn(sh[t], sh[t + s]);
        __syncthreads();
    }
    if (t == 0) out[(size_t)N_ROWS * D + N_ROWS] = expf(-sh[0]);
}

extern "C" void kernel_launch(void* const* d_in, const int* in_sizes, int n_in,
                              void* d_out, int out_size) {
    const float* z      = (const float*)d_in[0];
    const float* cb     = (const float*)d_in[1];
    const float* dither = (const float*)d_in[2];
    const float* n1     = (const float*)d_in[3];
    const float* n2     = (const float*)d_in[4];
    float* out = (float*)d_out;

    split_kernel<<<(KFULL * D + 255) / 256, 256>>>(cb, dither);
    cj_kernel<<<KFULL / 128, 128>>>();
    main_kernel<<<N_ROWS / ROWS_PER_CTA, TPB>>>(z, cb, dither, n1, n2, out);
    perp_kernel<<<1, 1024>>>(out);
}

// round 9
// speedup vs baseline: 3.0457x; 1.1415x over previous
#include <cuda_runtime.h>
#include <cuda_bf16.h>
#include <cstdint>

#define N_ROWS 131072
#define D      64
#define KFULL  1024
#define KM1    1023
#define TPB    128
#define ROWS_PER_CTA 128
#define CHUNK  64
#define NCHUNK (KFULL / CHUNK)
#define BSTR   72            // padded bf16 stride per code row (conflict-free)

// device scratch (no dynamic allocation allowed)
__device__ float          g_dith[KFULL * D];   // exact dithered codebook
__device__ __nv_bfloat16  g_dhb[KFULL * D];    // bf16 hi
__device__ float          g_cj[KFULL];         // ||d_j||^2 locked; [>=1023]=1e30
__device__ int            g_counts[KFULL];

// ---------------- helpers ----------------
__device__ __forceinline__ uint32_t bfpack2(float2 v) {
    uint32_t r;
    asm("cvt.rn.bf16x2.f32 %0, %1, %2;" : "=r"(r) : "f"(v.y), "f"(v.x));
    return r;
}
__device__ __forceinline__ void mma16(float* d, const uint32_t* a,
                                      uint32_t b0, uint32_t b1) {
    asm volatile(
        "mma.sync.aligned.m16n8k16.row.col.f32.bf16.bf16.f32 "
        "{%0,%1,%2,%3}, {%4,%5,%6,%7}, {%8,%9}, {%0,%1,%2,%3};"
        : "+f"(d[0]), "+f"(d[1]), "+f"(d[2]), "+f"(d[3])
        : "r"(a[0]), "r"(a[1]), "r"(a[2]), "r"(a[3]), "r"(b0), "r"(b1));
}
__device__ __forceinline__ void ins3(float (&ms)[3], int (&mj)[3], float s, int j) {
    if (s < ms[2]) {
        if (s < ms[1]) {
            ms[2] = ms[1]; mj[2] = mj[1];
            if (s < ms[0]) { ms[1] = ms[0]; mj[1] = mj[0]; ms[0] = s; mj[0] = j; }
            else           { ms[1] = s; mj[1] = j; }
        } else { ms[2] = s; mj[2] = j; }
    }
}

// ---------- prep 1: elementwise dithered codebook + bf16 hi ----------
__global__ void split_kernel(const float* __restrict__ cb,
                             const float* __restrict__ dither) {
    int idx = blockIdx.x * blockDim.x + threadIdx.x;
    if (idx >= KFULL * D) return;
    int j = idx >> 6;
    float dv = 0.0f;
    if (j < KM1) {
        int k = idx & 63;
        float lo = cb[j * D + k];
        float hi = cb[(j + 1) * D + k];
        dv = __fadd_rn(lo, __fmul_rn(dither[j], __fsub_rn(hi, lo)));
    }
    g_dith[idx] = dv;
    g_dhb[idx] = __float2bfloat16_rn(dv);
    if (idx < KFULL) g_counts[idx] = 0;
}

// ---------- prep 2: ||d_j||^2 locked sequential ----------
__global__ void cj_kernel() {
    int j = blockIdx.x * blockDim.x + threadIdx.x;
    if (j >= KFULL) return;
    if (j >= KM1) { g_cj[j] = 1e30f; return; }
    float acc = 0.0f;
    #pragma unroll 8
    for (int k = 0; k < D; k++) {
        float d = g_dith[j * D + k];
        acc = __fadd_rn(acc, __fmul_rn(d, d));
    }
    g_cj[j] = acc;
}

// ---------- main: 1-pass bf16 mma prefilter + exact rescore + epilogue ----------
__global__ void __launch_bounds__(TPB)
main_kernel(const float* __restrict__ z,
            const float* __restrict__ cb,
            const float* __restrict__ dither,
            const float* __restrict__ n1,
            const float* __restrict__ n2,
            float* __restrict__ out) {
    __shared__ __align__(16) __nv_bfloat16 sh_bh[CHUNK * BSTR];  // 9216 B
    __shared__ float sh_cj[CHUNK];
    __shared__ float sh_cs[ROWS_PER_CTA * 12];
    __shared__ int   sh_ci[ROWS_PER_CTA * 12];

    const int tid  = threadIdx.x;
    const int w    = tid >> 5;
    const int lane = tid & 31;
    const int g    = lane >> 2;
    const int tig  = lane & 3;

    // ---- A fragments: 32 z-rows per warp, bf16 hi only, m16n8k16 layout ----
    const float* zb = z + (size_t)(blockIdx.x * ROWS_PER_CTA + w * 32) * D;
    uint32_t ah[2][4][4];
    #pragma unroll
    for (int m = 0; m < 2; m++) {
        #pragma unroll
        for (int s = 0; s < 4; s++) {
            int r0 = m * 16 + g, r1 = r0 + 8;
            int kb = s * 16 + tig * 2;
            ah[m][s][0] = bfpack2(*(const float2*)(zb + r0 * D + kb));
            ah[m][s][1] = bfpack2(*(const float2*)(zb + r1 * D + kb));
            ah[m][s][2] = bfpack2(*(const float2*)(zb + r0 * D + kb + 8));
            ah[m][s][3] = bfpack2(*(const float2*)(zb + r1 * D + kb + 8));
        }
    }

    float ms[4][3];
    int   mj[4][3];
    #pragma unroll
    for (int r = 0; r < 4; r++)
        #pragma unroll
        for (int k = 0; k < 3; k++) { ms[r][k] = 3.4e38f; mj[r][k] = 0; }

    for (int ch = 0; ch < NCHUNK; ch++) {
        __syncthreads();
        // stage 64 codes (bf16 hi) into padded shared + cj
        {
            const uint2* srcH = (const uint2*)(g_dhb + (size_t)ch * CHUNK * D);
            #pragma unroll
            for (int i = 0; i < 8; i++) {
                int q = tid + i * TPB;        // uint2 index: 64 codes x 16
                int code = q >> 4, kq = q & 15;
                *(uint2*)(sh_bh + code * BSTR + kq * 4) = srcH[q];
            }
            if (tid < CHUNK) sh_cj[tid] = g_cj[ch * CHUNK + tid];
        }
        __syncthreads();

        for (int t = 0; t < 8; t++) {
            float acc0[4] = {0.f, 0.f, 0.f, 0.f};
            float acc1[4] = {0.f, 0.f, 0.f, 0.f};
            #pragma unroll
            for (int s = 0; s < 4; s++) {
                const __nv_bfloat16* bp = sh_bh + (t * 8 + g) * BSTR + s * 16 + tig * 2;
                uint32_t bh0 = *(const uint32_t*)bp;
                uint32_t bh1 = *(const uint32_t*)(bp + 8);
                mma16(acc0, ah[0][s], bh0, bh1);
                mma16(acc1, ah[1][s], bh0, bh1);
            }
            int j0 = ch * CHUNK + t * 8 + tig * 2;
            int j1 = j0 + 1;
            float cj0 = sh_cj[t * 8 + tig * 2];
            float cj1 = sh_cj[t * 8 + tig * 2 + 1];
            ins3(ms[0], mj[0], __fmaf_rn(-2.f, acc0[0], cj0), j0);
            ins3(ms[0], mj[0], __fmaf_rn(-2.f, acc0[1], cj1), j1);
            ins3(ms[1], mj[1], __fmaf_rn(-2.f, acc0[2], cj0), j0);
            ins3(ms[1], mj[1], __fmaf_rn(-2.f, acc0[3], cj1), j1);
            ins3(ms[2], mj[2], __fmaf_rn(-2.f, acc1[0], cj0), j0);
            ins3(ms[2], mj[2], __fmaf_rn(-2.f, acc1[1], cj1), j1);
            ins3(ms[3], mj[3], __fmaf_rn(-2.f, acc1[2], cj0), j0);
            ins3(ms[3], mj[3], __fmaf_rn(-2.f, acc1[3], cj1), j1);
        }
    }

    #pragma unroll
    for (int r = 0; r < 4; r++) {
        int lrow = w * 32 + (r >> 1) * 16 + (r & 1) * 8 + g;
        int base = lrow * 12 + tig * 3;
        #pragma unroll
        for (int k = 0; k < 3; k++) { sh_cs[base + k] = ms[r][k]; sh_ci[base + k] = mj[r][k]; }
    }
    __syncthreads();

    // ---------- exact rescore (locked numerics) ----------
    const int row = blockIdx.x * ROWS_PER_CTA + tid;
    float zr[D];
    {
        const float4* zp = (const float4*)(z + (size_t)row * D);
        #pragma unroll
        for (int q = 0; q < 16; q++) {
            float4 v = zp[q];
            zr[4 * q + 0] = v.x; zr[4 * q + 1] = v.y;
            zr[4 * q + 2] = v.z; zr[4 * q + 3] = v.w;
        }
    }
    float nz = 0.0f;
    #pragma unroll
    for (int k = 0; k < D; k++) nz = __fadd_rn(nz, __fmul_rn(zr[k], zr[k]));

    float minf = 3.4e38f;
    #pragma unroll
    for (int k = 0; k < 12; k++) minf = fminf(minf, sh_cs[tid * 12 + k]);
    const float thr = minf + 2.4e-4f;

    float best = 3.4e38f;
    int   bj   = 0x7FFFFFFF;
    for (int k = 0; k < 12; k++) {
        float fs = sh_cs[tid * 12 + k];
        if (fs <= thr) {
            int j = sh_ci[tid * 12 + k];
            const float* dj = g_dith + (size_t)j * D;
            float c0 = 0.f, c1 = 0.f, c2 = 0.f, c3 = 0.f;
            float c4 = 0.f, c5 = 0.f, c6 = 0.f, c7 = 0.f;
            #pragma unroll
            for (int kk = 0; kk < D; kk += 8) {
                c0 = __fmaf_rn(zr[kk + 0], dj[kk + 0], c0);
                c1 = __fmaf_rn(zr[kk + 1], dj[kk + 1], c1);
                c2 = __fmaf_rn(zr[kk + 2], dj[kk + 2], c2);
                c3 = __fmaf_rn(zr[kk + 3], dj[kk + 3], c3);
                c4 = __fmaf_rn(zr[kk + 4], dj[kk + 4], c4);
                c5 = __fmaf_rn(zr[kk + 5], dj[kk + 5], c5);
                c6 = __fmaf_rn(zr[kk + 6], dj[kk + 6], c6);
                c7 = __fmaf_rn(zr[kk + 7], dj[kk + 7], c7);
            }
            float dot = __fadd_rn(
                __fadd_rn(__fadd_rn(c0, c1), __fadd_rn(c2, c3)),
                __fadd_rn(__fadd_rn(c4, c5), __fadd_rn(c6, c7)));
            float s = __fsub_rn(__fadd_rn(nz, g_cj[j]), __fmul_rn(2.0f, dot));
            if (s < best || (s == best && j < bj)) { best = s; bj = j; }
        }
    }

    // ---------- epilogue (proven R2 numerics) ----------
    {
        const int i = bj;
        const float2* cfp = (const float2*)(cb + (size_t)i * D);
        const float2* csp = (const float2*)(cb + (size_t)(i + 1) * D);
        const float2* ap  = (const float2*)(n1 + (size_t)row * D);
        const float2* bp  = (const float2*)(n2 + (size_t)row * D);
        const float lam = dither[i];

        float sd1 = 0.0f, sr1 = 0.0f, sd2 = 0.0f, sr2 = 0.0f;
        #pragma unroll
        for (int q = 0; q < 32; q++) {
            float zx = zr[2 * q], zy = zr[2 * q + 1];
            float2 cf = cfp[q], cs = csp[q], av = ap[q], bv = bp[q];
            {
                float d1 = __fsub_rn(cf.x, zx);
                float r1 = __fadd_rn(av.x, d1);
                sd1 = __fadd_rn(sd1, __fmul_rn(d1, d1));
                sr1 = __fadd_rn(sr1, __fmul_rn(r1, r1));
                float d2 = __fsub_rn(cs.x, zx);
                float r2 = __fadd_rn(bv.x, d2);
                sd2 = __fadd_rn(sd2, __fmul_rn(d2, d2));
                sr2 = __fadd_rn(sr2, __fmul_rn(r2, r2));
            }
            {
                float d1 = __fsub_rn(cf.y, zy);
                float r1 = __fadd_rn(av.y, d1);
                sd1 = __fadd_rn(sd1, __fmul_rn(d1, d1));
                sr1 = __fadd_rn(sr1, __fmul_rn(r1, r1));
                float d2 = __fsub_rn(cs.y, zy);
                float r2 = __fadd_rn(bv.y, d2);
                sd2 = __fadd_rn(sd2, __fmul_rn(d2, d2));
                sr2 = __fadd_rn(sr2, __fmul_rn(r2, r2));
            }
        }

        float nn1 = fmaxf(__fsqrt_rn(sr1), 1e-12f);
        float nn2 = fmaxf(__fsqrt_rn(sr2), 1e-12f);
        float em1 = __fsqrt_rn(sd1);
        float em2 = __fsqrt_rn(sd2);
        float s1  = __fsub_rn(1.0f, lam);

        float2* op = (float2*)(out + (size_t)row * D);
        #pragma unroll
        for (int q = 0; q < 32; q++) {
            float zx = zr[2 * q], zy = zr[2 * q + 1];
            float2 cf = cfp[q], cs = csp[q], av = ap[q], bv = bp[q];
            float2 o;
            {
                float d1 = __fsub_rn(cf.x, zx);
                float r1 = __fadd_rn(av.x, d1);
                float d2 = __fsub_rn(cs.x, zx);
                float r2 = __fadd_rn(bv.x, d2);
                float v1 = __fmul_rn(em1, __fmul_rn(s1,  __fdiv_rn(r1, nn1)));
                float v2 = __fmul_rn(em2, __fmul_rn(lam, __fdiv_rn(r2, nn2)));
                o.x = __fadd_rn(__fadd_rn(zx, v1), v2);
            }
            {
                float d1 = __fsub_rn(cf.y, zy);
                float r1 = __fadd_rn(av.y, d1);
                float d2 = __fsub_rn(cs.y, zy);
                float r2 = __fadd_rn(bv.y, d2);
                float v1 = __fmul_rn(em1, __fmul_rn(s1,  __fdiv_rn(r1, nn1)));
                float v2 = __fmul_rn(em2, __fmul_rn(lam, __fdiv_rn(r2, nn2)));
                o.y = __fadd_rn(__fadd_rn(zy, v1), v2);
            }
            op[q] = o;
        }

        out[(size_t)N_ROWS * D + row] = (float)i;
        atomicAdd(&g_counts[i], 1);
    }
}

// ---------- perplexity ----------
__global__ void perp_kernel(float* __restrict__ out) {
    __shared__ float sh[1024];
    int t = threadIdx.x;
    float p = (float)g_counts[t] * (1.0f / 131072.0f);
    sh[t] = (p > 0.0f) ? __fmul_rn(p, logf(p)) : 0.0f;
    __syncthreads();
    for (int s = 512; s > 0; s >>= 1) {
        if (t < s) sh[t] = __fadd_rn(sh[t], sh[t + s]);
        __syncthreads();
    }
    if (t == 0) out[(size_t)N_ROWS * D + N_ROWS] = expf(-sh[0]);
}

extern "C" void kernel_launch(void* const* d_in, const int* in_sizes, int n_in,
                              void* d_out, int out_size) {
    const float* z      = (const float*)d_in[0];
    const float* cb     = (const float*)d_in[1];
    const float* dither = (const float*)d_in[2];
    const float* n1     = (const float*)d_in[3];
    const float* n2     = (const float*)d_in[4];
    float* out = (float*)d_out;

    split_kernel<<<(KFULL * D + 255) / 256, 256>>>(cb, dither);
    cj_kernel<<<KFULL / 128, 128>>>();
    main_kernel<<<N_ROWS / ROWS_PER_CTA, TPB>>>(z, cb, dither, n1, n2, out);
    perp_kernel<<<1, 1024>>>(out);
}

// round 10
// speedup vs baseline: 5.3039x; 1.7414x over previous
#include <cuda_runtime.h>
#include <cuda_bf16.h>
#include <cstdint>

#define N_ROWS 131072
#define D      64
#define KFULL  1024
#define KM1    1023
#define TPB    128
#define ROWS_PER_CTA 128
#define CHUNK  64
#define NCHUNK (KFULL / CHUNK)
#define BSTR   72            // padded bf16 stride per code row (conflict-free)
#define KEYMASK 0xFFFFFC00

// device scratch (no dynamic allocation allowed)
__device__ float          g_dith[KFULL * D];   // exact dithered codebook
__device__ __nv_bfloat16  g_dhb[KFULL * D];    // bf16 hi
__device__ float          g_cj[KFULL];         // exact ||d||^2; [1023]=1e30
__device__ float          g_cjq[KFULL];        // cj + 0.75 (key bias); [1023]=0.95
__device__ int            g_counts[KFULL];
__device__ unsigned       g_done;

// ---------------- helpers ----------------
__device__ __forceinline__ uint32_t bfpack2(float2 v) {
    uint32_t r;
    asm("cvt.rn.bf16x2.f32 %0, %1, %2;" : "=r"(r) : "f"(v.y), "f"(v.x));
    return r;
}
__device__ __forceinline__ void mma16(float* d, const uint32_t* a,
                                      uint32_t b0, uint32_t b1) {
    asm volatile(
        "mma.sync.aligned.m16n8k16.row.col.f32.bf16.bf16.f32 "
        "{%0,%1,%2,%3}, {%4,%5,%6,%7}, {%8,%9}, {%0,%1,%2,%3};"
        : "+f"(d[0]), "+f"(d[1]), "+f"(d[2]), "+f"(d[3])
        : "r"(a[0]), "r"(a[1]), "r"(a[2]), "r"(a[3]), "r"(b0), "r"(b1));
}
// branchless merge of sorted pair (klo<=khi) into sorted top-3 (m0<=m1<=m2)
__device__ __forceinline__ void merge3(int& m0, int& m1, int& m2,
                                       int k0, int k1) {
    int klo = min(k0, k1);
    int khi = max(k0, k1);
    int r0 = min(m0, klo);
    int x  = max(m0, klo);
    int r1 = min(min(x, m1), khi);
    int mk = min(m1, khi);
    int Mk = max(m1, khi);
    int xm = max(x, mk);
    int r2 = min(min(Mk, xm), m2);
    m0 = r0; m1 = r1; m2 = r2;
}

// ---------- prep 1: elementwise dithered codebook + bf16 hi ----------
__global__ void split_kernel(const float* __restrict__ cb,
                             const float* __restrict__ dither) {
    int idx = blockIdx.x * blockDim.x + threadIdx.x;
    if (idx >= KFULL * D) return;
    int j = idx >> 6;
    float dv = 0.0f;
    if (j < KM1) {
        int k = idx & 63;
        float lo = cb[j * D + k];
        float hi = cb[(j + 1) * D + k];
        dv = __fadd_rn(lo, __fmul_rn(dither[j], __fsub_rn(hi, lo)));
    }
    g_dith[idx] = dv;
    g_dhb[idx] = __float2bfloat16_rn(dv);
    if (idx < KFULL) g_counts[idx] = 0;
    if (idx == 0) g_done = 0u;
}

// ---------- prep 2: ||d_j||^2 locked sequential + key bias ----------
__global__ void cj_kernel() {
    int j = blockIdx.x * blockDim.x + threadIdx.x;
    if (j >= KFULL) return;
    if (j >= KM1) { g_cj[j] = 1e30f; g_cjq[j] = 0.95f; return; }
    float acc = 0.0f;
    #pragma unroll 8
    for (int k = 0; k < D; k++) {
        float d = g_dith[j * D + k];
        acc = __fadd_rn(acc, __fmul_rn(d, d));
    }
    g_cj[j] = acc;
    g_cjq[j] = acc + 0.75f;
}

// ---------- main: 1-pass bf16 prefilter (packed keys) + rescore + epilogue ----------
__global__ void __launch_bounds__(TPB)
main_kernel(const float* __restrict__ z,
            const float* __restrict__ cb,
            const float* __restrict__ dither,
            const float* __restrict__ n1,
            const float* __restrict__ n2,
            float* __restrict__ out) {
    __shared__ __align__(16) __nv_bfloat16 sh_bh[2][CHUNK * BSTR];  // 18432 B
    __shared__ float sh_cq[2][CHUNK];
    __shared__ int   sh_ck[ROWS_PER_CTA * 12];
    __shared__ int   s_last;
    __shared__ float red[TPB];

    const int tid  = threadIdx.x;
    const int w    = tid >> 5;
    const int lane = tid & 31;
    const int g    = lane >> 2;
    const int tig  = lane & 3;

    // ---- A fragments: 32 z-rows per warp, bf16 hi, m16n8k16 layout ----
    const float* zb = z + (size_t)(blockIdx.x * ROWS_PER_CTA + w * 32) * D;
    uint32_t ah[2][4][4];
    #pragma unroll
    for (int m = 0; m < 2; m++) {
        #pragma unroll
        for (int s = 0; s < 4; s++) {
            int r0 = m * 16 + g, r1 = r0 + 8;
            int kb = s * 16 + tig * 2;
            ah[m][s][0] = bfpack2(*(const float2*)(zb + r0 * D + kb));
            ah[m][s][1] = bfpack2(*(const float2*)(zb + r1 * D + kb));
            ah[m][s][2] = bfpack2(*(const float2*)(zb + r0 * D + kb + 8));
            ah[m][s][3] = bfpack2(*(const float2*)(zb + r1 * D + kb + 8));
        }
    }

    // top-3 packed keys per (row-slot)
    int m0[4], m1[4], m2[4];
    #pragma unroll
    for (int r = 0; r < 4; r++) { m0[r] = 0x7FFFFFFF; m1[r] = 0x7FFFFFFF; m2[r] = 0x7FFFFFFF; }

    // prologue: stage chunk 0 into buffer 0
    {
        const uint2* srcH = (const uint2*)g_dhb;
        #pragma unroll
        for (int i = 0; i < 8; i++) {
            int q = tid + i * TPB;
            *(uint2*)(&sh_bh[0][(q >> 4) * BSTR + (q & 15) * 4]) = srcH[q];
        }
        if (tid < CHUNK) sh_cq[0][tid] = g_cjq[tid];
    }
    __syncthreads();

    for (int ch = 0; ch < NCHUNK; ch++) {
        const int cur = ch & 1;
        const int base = ch * CHUNK;

        // prefetch next chunk into registers
        uint2 rH[8];
        float rc = 0.0f;
        if (ch + 1 < NCHUNK) {
            const uint2* srcH = (const uint2*)(g_dhb + (size_t)(ch + 1) * CHUNK * D);
            #pragma unroll
            for (int i = 0; i < 8; i++) rH[i] = srcH[tid + i * TPB];
            if (tid < CHUNK) rc = g_cjq[(ch + 1) * CHUNK + tid];
        }

        #pragma unroll
        for (int t = 0; t < 8; t++) {
            float acc0[4] = {0.f, 0.f, 0.f, 0.f};
            float acc1[4] = {0.f, 0.f, 0.f, 0.f};
            #pragma unroll
            for (int s = 0; s < 4; s++) {
                const __nv_bfloat16* bp = &sh_bh[cur][(t * 8 + g) * BSTR + s * 16 + tig * 2];
                uint32_t bh0 = *(const uint32_t*)bp;
                uint32_t bh1 = *(const uint32_t*)(bp + 8);
                mma16(acc0, ah[0][s], bh0, bh1);
                mma16(acc1, ah[1][s], bh0, bh1);
            }
            const int j0 = base + t * 8 + tig * 2;
            const float cq0 = sh_cq[cur][t * 8 + tig * 2];
            const float cq1 = sh_cq[cur][t * 8 + tig * 2 + 1];
            // packed keys: (bits(f + 0.75) & ~0x3FF) | j  — int-monotonic
            int k00 = (__float_as_int(__fmaf_rn(-2.f, acc0[0], cq0)) & KEYMASK) | j0;
            int k01 = (__float_as_int(__fmaf_rn(-2.f, acc0[1], cq1)) & KEYMASK) | (j0 + 1);
            int k02 = (__float_as_int(__fmaf_rn(-2.f, acc0[2], cq0)) & KEYMASK) | j0;
            int k03 = (__float_as_int(__fmaf_rn(-2.f, acc0[3], cq1)) & KEYMASK) | (j0 + 1);
            int k10 = (__float_as_int(__fmaf_rn(-2.f, acc1[0], cq0)) & KEYMASK) | j0;
            int k11 = (__float_as_int(__fmaf_rn(-2.f, acc1[1], cq1)) & KEYMASK) | (j0 + 1);
            int k12 = (__float_as_int(__fmaf_rn(-2.f, acc1[2], cq0)) & KEYMASK) | j0;
            int k13 = (__float_as_int(__fmaf_rn(-2.f, acc1[3], cq1)) & KEYMASK) | (j0 + 1);
            merge3(m0[0], m1[0], m2[0], k00, k01);
            merge3(m0[1], m1[1], m2[1], k02, k03);
            merge3(m0[2], m1[2], m2[2], k10, k11);
            merge3(m0[3], m1[3], m2[3], k12, k13);
        }

        // store prefetched chunk into the other buffer
        if (ch + 1 < NCHUNK) {
            const int nxt = cur ^ 1;
            #pragma unroll
            for (int i = 0; i < 8; i++) {
                int q = tid + i * TPB;
                *(uint2*)(&sh_bh[nxt][(q >> 4) * BSTR + (q & 15) * 4]) = rH[i];
            }
            if (tid < CHUNK) sh_cq[nxt][tid] = rc;
        }
        __syncthreads();
    }

    // candidate keys to shared: 4 tig x 3 per row
    #pragma unroll
    for (int r = 0; r < 4; r++) {
        int lrow = w * 32 + (r >> 1) * 16 + (r & 1) * 8 + g;
        int bb = lrow * 12 + tig * 3;
        sh_ck[bb + 0] = m0[r];
        sh_ck[bb + 1] = m1[r];
        sh_ck[bb + 2] = m2[r];
    }
    __syncthreads();

    // ---------- exact rescore (locked numerics) ----------
    const int row = blockIdx.x * ROWS_PER_CTA + tid;
    float zr[D];
    {
        const float4* zp = (const float4*)(z + (size_t)row * D);
        #pragma unroll
        for (int q = 0; q < 16; q++) {
            float4 v = zp[q];
            zr[4 * q + 0] = v.x; zr[4 * q + 1] = v.y;
            zr[4 * q + 2] = v.z; zr[4 * q + 3] = v.w;
        }
    }
    float nz = 0.0f;
    #pragma unroll
    for (int k = 0; k < D; k++) nz = __fadd_rn(nz, __fmul_rn(zr[k], zr[k]));

    int mink = 0x7FFFFFFF;
    #pragma unroll
    for (int k = 0; k < 12; k++) mink = min(mink, sh_ck[tid * 12 + k]);
    const float thrf = __int_as_float(mink & KEYMASK) + 4e-4f;

    float best = 3.4e38f;
    int   bj   = 0x7FFFFFFF;
    for (int k = 0; k < 12; k++) {
        int kk0 = sh_ck[tid * 12 + k];
        if (__int_as_float(kk0) <= thrf) {
            int j = kk0 & 1023;
            const float* dj = g_dith + (size_t)j * D;
            float c0 = 0.f, c1 = 0.f, c2 = 0.f, c3 = 0.f;
            float c4 = 0.f, c5 = 0.f, c6 = 0.f, c7 = 0.f;
            #pragma unroll
            for (int q = 0; q < D; q += 8) {
                c0 = __fmaf_rn(zr[q + 0], dj[q + 0], c0);
                c1 = __fmaf_rn(zr[q + 1], dj[q + 1], c1);
                c2 = __fmaf_rn(zr[q + 2], dj[q + 2], c2);
                c3 = __fmaf_rn(zr[q + 3], dj[q + 3], c3);
                c4 = __fmaf_rn(zr[q + 4], dj[q + 4], c4);
                c5 = __fmaf_rn(zr[q + 5], dj[q + 5], c5);
                c6 = __fmaf_rn(zr[q + 6], dj[q + 6], c6);
                c7 = __fmaf_rn(zr[q + 7], dj[q + 7], c7);
            }
            float dot = __fadd_rn(
                __fadd_rn(__fadd_rn(c0, c1), __fadd_rn(c2, c3)),
                __fadd_rn(__fadd_rn(c4, c5), __fadd_rn(c6, c7)));
            float s = __fsub_rn(__fadd_rn(nz, g_cj[j]), __fmul_rn(2.0f, dot));
            if (s < best || (s == best && j < bj)) { best = s; bj = j; }
        }
    }

    // ---------- epilogue (proven R2 numerics) ----------
    {
        const int i = bj;
        const float2* cfp = (const float2*)(cb + (size_t)i * D);
        const float2* csp = (const float2*)(cb + (size_t)(i + 1) * D);
        const float2* ap  = (const float2*)(n1 + (size_t)row * D);
        const float2* bp  = (const float2*)(n2 + (size_t)row * D);
        const float lam = dither[i];

        float sd1 = 0.0f, sr1 = 0.0f, sd2 = 0.0f, sr2 = 0.0f;
        #pragma unroll
        for (int q = 0; q < 32; q++) {
            float zx = zr[2 * q], zy = zr[2 * q + 1];
            float2 cf = cfp[q], cs = csp[q], av = ap[q], bv = bp[q];
            {
                float d1 = __fsub_rn(cf.x, zx);
                float r1 = __fadd_rn(av.x, d1);
                sd1 = __fadd_rn(sd1, __fmul_rn(d1, d1));
                sr1 = __fadd_rn(sr1, __fmul_rn(r1, r1));
                float d2 = __fsub_rn(cs.x, zx);
                float r2 = __fadd_rn(bv.x, d2);
                sd2 = __fadd_rn(sd2, __fmul_rn(d2, d2));
                sr2 = __fadd_rn(sr2, __fmul_rn(r2, r2));
            }
            {
                float d1 = __fsub_rn(cf.y, zy);
                float r1 = __fadd_rn(av.y, d1);
                sd1 = __fadd_rn(sd1, __fmul_rn(d1, d1));
                sr1 = __fadd_rn(sr1, __fmul_rn(r1, r1));
                float d2 = __fsub_rn(cs.y, zy);
                float r2 = __fadd_rn(bv.y, d2);
                sd2 = __fadd_rn(sd2, __fmul_rn(d2, d2));
                sr2 = __fadd_rn(sr2, __fmul_rn(r2, r2));
            }
        }

        float nn1 = fmaxf(__fsqrt_rn(sr1), 1e-12f);
        float nn2 = fmaxf(__fsqrt_rn(sr2), 1e-12f);
        float em1 = __fsqrt_rn(sd1);
        float em2 = __fsqrt_rn(sd2);
        float s1  = __fsub_rn(1.0f, lam);

        float2* op = (float2*)(out + (size_t)row * D);
        #pragma unroll
        for (int q = 0; q < 32; q++) {
            float zx = zr[2 * q], zy = zr[2 * q + 1];
            float2 cf = cfp[q], cs = csp[q], av = ap[q], bv = bp[q];
            float2 o;
            {
                float d1 = __fsub_rn(cf.x, zx);
                float r1 = __fadd_rn(av.x, d1);
                float d2 = __fsub_rn(cs.x, zx);
                float r2 = __fadd_rn(bv.x, d2);
                float v1 = __fmul_rn(em1, __fmul_rn(s1,  __fdiv_rn(r1, nn1)));
                float v2 = __fmul_rn(em2, __fmul_rn(lam, __fdiv_rn(r2, nn2)));
                o.x = __fadd_rn(__fadd_rn(zx, v1), v2);
            }
            {
                float d1 = __fsub_rn(cf.y, zy);
                float r1 = __fadd_rn(av.y, d1);
                float d2 = __fsub_rn(cs.y, zy);
                float r2 = __fadd_rn(bv.y, d2);
                float v1 = __fmul_rn(em1, __fmul_rn(s1,  __fdiv_rn(r1, nn1)));
                float v2 = __fmul_rn(em2, __fmul_rn(lam, __fdiv_rn(r2, nn2)));
                o.y = __fadd_rn(__fadd_rn(zy, v1), v2);
            }
            op[q] = o;
        }

        out[(size_t)N_ROWS * D + row] = (float)i;
        atomicAdd(&g_counts[i], 1);
    }

    // ---------- fused perplexity: last CTA reduces ----------
    __threadfence();
    __syncthreads();
    if (tid == 0) {
        unsigned v = atomicAdd(&g_done, 1u);
        s_last = (v == (unsigned)(gridDim.x - 1)) ? 1 : 0;
    }
    __syncthreads();
    if (s_last) {
        float part = 0.0f;
        #pragma unroll
        for (int t = tid; t < KFULL; t += TPB) {
            float p = (float)__ldcg(&g_counts[t]) * (1.0f / 131072.0f);
            part = __fadd_rn(part, (p > 0.0f) ? __fmul_rn(p, logf(p)) : 0.0f);
        }
        red[tid] = part;
        __syncthreads();
        for (int s = TPB / 2; s > 0; s >>= 1) {
            if (tid < s) red[tid] = __fadd_rn(red[tid], red[tid + s]);
            __syncthreads();
        }
        if (tid == 0) out[(size_t)N_ROWS * D + N_ROWS] = expf(-red[0]);
    }
}

extern "C" void kernel_launch(void* const* d_in, const int* in_sizes, int n_in,
                              void* d_out, int out_size) {
    const float* z      = (const float*)d_in[0];
    const float* cb     = (const float*)d_in[1];
    const float* dither = (const float*)d_in[2];
    const float* n1     = (const float*)d_in[3];
    const float* n2     = (const float*)d_in[4];
    float* out = (float*)d_out;

    split_kernel<<<(KFULL * D + 255) / 256, 256>>>(cb, dither);
    cj_kernel<<<KFULL / 128, 128>>>();
    main_kernel<<<N_ROWS / ROWS_PER_CTA, TPB>>>(z, cb, dither, n1, n2, out);
}